// round 10
// baseline (speedup 1.0000x reference)
#include <cuda_runtime.h>
#include <cstdint>

#define B 8
#define TE 512
#define TD 256
#define H 256

typedef unsigned long long ull;

// Scratch (device globals: no allocations allowed)
__device__ float g_WeT[B * H * TE];  // [b][h][i]
__device__ float g_Uh [B * TD * H];  // [b][j][h]

__device__ __forceinline__ float tanh_fast(float x) {
    float y;
    asm("tanh.approx.f32 %0, %1;" : "=f"(y) : "f"(x));
    return y;
}

// ---- packed fp32x2 helpers ----
__device__ __forceinline__ ull pk2(float lo, float hi) {
    ull r; asm("mov.b64 %0, {%1, %2};" : "=l"(r) : "f"(lo), "f"(hi)); return r;
}
__device__ __forceinline__ ull fma2(ull a, ull b, ull c) {
    ull d; asm("fma.rn.f32x2 %0, %1, %2, %3;" : "=l"(d) : "l"(a), "l"(b), "l"(c)); return d;
}
__device__ __forceinline__ void upk2(ull v, float& lo, float& hi) {
    asm("mov.b64 {%0, %1}, %2;" : "=f"(lo), "=f"(hi) : "l"(v));
}

// 4x4 micro-tile step, rows packed in pairs, cols duplicated
__device__ __forceinline__ void micro_fma2(ull acc2[2][4], float4 a, float4 bb) {
    ull pa0 = pk2(a.x, a.y);
    ull pa1 = pk2(a.z, a.w);
    ull pb0 = pk2(bb.x, bb.x);
    ull pb1 = pk2(bb.y, bb.y);
    ull pb2 = pk2(bb.z, bb.z);
    ull pb3 = pk2(bb.w, bb.w);
    acc2[0][0] = fma2(pa0, pb0, acc2[0][0]);
    acc2[0][1] = fma2(pa0, pb1, acc2[0][1]);
    acc2[0][2] = fma2(pa0, pb2, acc2[0][2]);
    acc2[0][3] = fma2(pa0, pb3, acc2[0][3]);
    acc2[1][0] = fma2(pa1, pb0, acc2[1][0]);
    acc2[1][1] = fma2(pa1, pb1, acc2[1][1]);
    acc2[1][2] = fma2(pa1, pb2, acc2[1][2]);
    acc2[1][3] = fma2(pa1, pb3, acc2[1][3]);
}

// ---------------------------------------------------------------------------
// Fused GEMM, double-buffered (unchanged from R5/R9 passing version).
// ---------------------------------------------------------------------------
__global__ __launch_bounds__(256) void gemm_fused(const float* __restrict__ enc,
                                                  const float* __restrict__ dec,
                                                  const float* __restrict__ W,
                                                  const float* __restrict__ U) {
    __shared__ float As[2][16][64];
    __shared__ float Bs[2][16][68];

    int b = blockIdx.z;
    int t = threadIdx.x;
    int tx = t & 15;
    int ty = t >> 4;

    ull acc2[2][4];
#pragma unroll
    for (int rp = 0; rp < 2; rp++)
#pragma unroll
        for (int c = 0; c < 4; c++) acc2[rp][c] = 0ull;

    bool weT = (blockIdx.x < 8);
    const float* Wm  = weT ? W : U;
    const float* act = weT ? (enc + (size_t)b * TE * H) : (dec + (size_t)b * TD * H);
    int h0 = blockIdx.y * 64;
    int c0 = weT ? blockIdx.x * 64 : (blockIdx.x - 8) * 64;

    int ka = t >> 4, hq = t & 15;
    int cc = t >> 2, kq = t & 3;

    {
        float4 aReg = *(const float4*)&Wm[ka * H + h0 + hq * 4];
        float4 bReg = *(const float4*)&act[(c0 + cc) * H + kq * 4];
        *(float4*)&As[0][ka][hq * 4] = aReg;
        Bs[0][kq * 4 + 0][cc] = bReg.x;
        Bs[0][kq * 4 + 1][cc] = bReg.y;
        Bs[0][kq * 4 + 2][cc] = bReg.z;
        Bs[0][kq * 4 + 3][cc] = bReg.w;
    }
    __syncthreads();

    if (weT) {
#pragma unroll 1
        for (int kt = 0; kt < 16; kt++) {
            int cur = kt & 1;
            float4 aReg, bReg;
            if (kt < 15) {
                int k0 = (kt + 1) * 16;
                aReg = *(const float4*)&Wm[(k0 + ka) * H + h0 + hq * 4];
                bReg = *(const float4*)&act[(c0 + cc) * H + k0 + kq * 4];
            }
#pragma unroll
            for (int kk = 0; kk < 16; kk++) {
                float4 a  = *(float4*)&As[cur][kk][ty * 4];
                float4 bb = *(float4*)&Bs[cur][kk][tx * 4];
                micro_fma2(acc2, a, bb);
            }
            if (kt < 15) {
                int nxt = cur ^ 1;
                *(float4*)&As[nxt][ka][hq * 4] = aReg;
                Bs[nxt][kq * 4 + 0][cc] = bReg.x;
                Bs[nxt][kq * 4 + 1][cc] = bReg.y;
                Bs[nxt][kq * 4 + 2][cc] = bReg.z;
                Bs[nxt][kq * 4 + 3][cc] = bReg.w;
                __syncthreads();
            }
        }
        float o[4][4];
#pragma unroll
        for (int rp = 0; rp < 2; rp++)
#pragma unroll
            for (int c = 0; c < 4; c++)
                upk2(acc2[rp][c], o[2 * rp][c], o[2 * rp + 1][c]);
        float* out = g_WeT + (size_t)b * H * TE;
#pragma unroll
        for (int r = 0; r < 4; r++) {
            float4 v = make_float4(o[r][0], o[r][1], o[r][2], o[r][3]);
            *(float4*)&out[(h0 + ty * 4 + r) * TE + c0 + tx * 4] = v;
        }
    } else {
#pragma unroll 1
        for (int kt = 0; kt < 16; kt++) {
            int cur = kt & 1;
            float4 aReg, bReg;
            if (kt < 15) {
                int k0 = (kt + 1) * 16;
                aReg = *(const float4*)&Wm[(k0 + ka) * H + h0 + hq * 4];
                bReg = *(const float4*)&act[(c0 + cc) * H + k0 + kq * 4];
            }
#pragma unroll
            for (int kk = 0; kk < 16; kk++) {
                float4 a  = *(float4*)&Bs[cur][kk][ty * 4];
                float4 bb = *(float4*)&As[cur][kk][tx * 4];
                micro_fma2(acc2, a, bb);
            }
            if (kt < 15) {
                int nxt = cur ^ 1;
                *(float4*)&As[nxt][ka][hq * 4] = aReg;
                Bs[nxt][kq * 4 + 0][cc] = bReg.x;
                Bs[nxt][kq * 4 + 1][cc] = bReg.y;
                Bs[nxt][kq * 4 + 2][cc] = bReg.z;
                Bs[nxt][kq * 4 + 3][cc] = bReg.w;
                __syncthreads();
            }
        }
        float o[4][4];
#pragma unroll
        for (int rp = 0; rp < 2; rp++)
#pragma unroll
            for (int c = 0; c < 4; c++)
                upk2(acc2[rp][c], o[2 * rp][c], o[2 * rp + 1][c]);
        float* out = g_Uh + (size_t)b * TD * H;
#pragma unroll
        for (int r = 0; r < 4; r++) {
            float4 v = make_float4(o[r][0], o[r][1], o[r][2], o[r][3]);
            *(float4*)&out[(c0 + ty * 4 + r) * H + h0 + tx * 4] = v;
        }
    }
}

// ---------------------------------------------------------------------------
// FUSED energy + softmax + context. JT=4 -> 512 blocks, 512 threads.
// Phase 2 (energy, f32 MUFU tanh) is the R5 passing code.
// Phase 4 (context) rides the idle fma pipe under the MUFU shadow.
// ---------------------------------------------------------------------------
__global__ __launch_bounds__(512) void attn_fused(const float* __restrict__ enc,
                                                  const float* __restrict__ Va,
                                                  float* __restrict__ c_out,
                                                  float* __restrict__ e_out) {
    __shared__ float Us4[H * 4];      // [h][jj]
    __shared__ float Vs[H];
    __shared__ float Ps[TE * 4];      // [i][jj] normalized probs (8 KB)
    __shared__ float red[16][4];
    __shared__ float binv[4];

    int t  = threadIdx.x;
    int b  = blockIdx.x >> 6;             // TD/4 = 64 tiles per batch
    int j0 = (blockIdx.x & 63) * 4;

    // ---- Phase 1: stage Uh tile (interleaved) + V ----
    for (int idx = t; idx < 4 * H; idx += 512) {
        int jj = idx >> 8;                // 0..3
        int h  = idx & (H - 1);
        Us4[h * 4 + jj] = g_Uh[((size_t)b * TD + j0 + jj) * H + h];
    }
    if (t < H) Vs[t] = Va[t];
    __syncthreads();

    // ---- Phase 2: energy (f32 tanh, MUFU floor) ----
    const int i = t;
    const float* wp = g_WeT + (size_t)b * H * TE + i;

    float acc0 = 0.f, acc1 = 0.f, acc2 = 0.f, acc3 = 0.f;
#pragma unroll 4
    for (int h = 0; h < H; h++) {
        float w = wp[h * TE];
        float4 u = *(const float4*)&Us4[h * 4];
        float v = Vs[h];
        acc0 = fmaf(v, tanh_fast(w + u.x), acc0);
        acc1 = fmaf(v, tanh_fast(w + u.y), acc1);
        acc2 = fmaf(v, tanh_fast(w + u.z), acc2);
        acc3 = fmaf(v, tanh_fast(w + u.w), acc3);
    }

    // ---- Phase 3: softmax over i (no max subtraction; |energy| <= ~13) ----
    float p0 = __expf(acc0);
    float p1 = __expf(acc1);
    float p2 = __expf(acc2);
    float p3 = __expf(acc3);

    int lane = t & 31, wrp = t >> 5;
    float s0 = p0, s1 = p1, s2 = p2, s3 = p3;
#pragma unroll
    for (int o = 16; o; o >>= 1) {
        s0 += __shfl_xor_sync(0xffffffffu, s0, o);
        s1 += __shfl_xor_sync(0xffffffffu, s1, o);
        s2 += __shfl_xor_sync(0xffffffffu, s2, o);
        s3 += __shfl_xor_sync(0xffffffffu, s3, o);
    }
    if (lane == 0) { red[wrp][0] = s0; red[wrp][1] = s1; red[wrp][2] = s2; red[wrp][3] = s3; }
    __syncthreads();
    if (t < 4) {
        float s = 0.f;
#pragma unroll
        for (int w2 = 0; w2 < 16; w2++) s += red[w2][t];
        binv[t] = 1.0f / s;
    }
    __syncthreads();

    float pn0 = p0 * binv[0];
    float pn1 = p1 * binv[1];
    float pn2 = p2 * binv[2];
    float pn3 = p3 * binv[3];

    float* e0 = e_out + ((size_t)b * TD + j0) * TE;
    e0[0 * TE + i] = pn0;
    e0[1 * TE + i] = pn1;
    e0[2 * TE + i] = pn2;
    e0[3 * TE + i] = pn3;
    // stash probs interleaved so phase 4 loads a j-pair with one LDS.64
    float4 pv = make_float4(pn0, pn1, pn2, pn3);
    *(float4*)&Ps[i * 4] = pv;
    __syncthreads();

    // ---- Phase 4: context  c[j][h] = sum_i P[j][i] * enc[b][i][h] ----
    // thread -> (h = t&255, g = t>>8).  g selects j-pair {2g, 2g+1}.
    int h  = t & (H - 1);
    int g  = t >> 8;                      // 0 or 1
    const float* ep = enc + (size_t)b * TE * H + h;

    ull cacc = 0ull;
#pragma unroll 4
    for (int i2 = 0; i2 < TE; i2++) {
        float e = ep[i2 * H];                       // coalesced over h
        ull pp = *(const ull*)&Ps[i2 * 4 + 2 * g];  // broadcast LDS.64 (j-pair)
        cacc = fma2(pp, pk2(e, e), cacc);
    }

    float clo, chi;
    upk2(cacc, clo, chi);
    float* cb = c_out + ((size_t)b * TD + j0 + 2 * g) * H + h;
    cb[0] = clo;
    cb[H] = chi;
}

// ---------------------------------------------------------------------------
extern "C" void kernel_launch(void* const* d_in, const int* in_sizes, int n_in,
                              void* d_out, int out_size) {
    const float* enc = (const float*)d_in[0];  // [B,TE,H]
    const float* dec = (const float*)d_in[1];  // [B,TD,H]
    const float* W   = (const float*)d_in[2];  // [H,H]
    const float* U   = (const float*)d_in[3];  // [H,H]
    const float* V   = (const float*)d_in[4];  // [H,1]

    float* c_out = (float*)d_out;              // [B,TD,H]
    float* e_out = (float*)d_out + B * TD * H; // [B,TD,TE]

    dim3 gg(12, 4, B);
    gemm_fused<<<gg, 256>>>(enc, dec, W, U);
    attn_fused<<<B * (TD / 4), 512>>>(enc, V, c_out, e_out);
}